// round 1
// baseline (speedup 1.0000x reference)
#include <cuda_runtime.h>

#define SEQ 2048
#define NB  32
#define DIM 128
#define NTOK (NB*SEQ)
#define TILE 64

// Scratch (no allocations allowed): ping-pong activation buffers + pool partials
__device__ float g_h0[NTOK*DIM];
__device__ float g_h1[NTOK*DIM];
__device__ float g_part[NB*8*DIM];

// ---------------------------------------------------------------------------
// Encoder: h = relu(x @ W1[6,128] + b1) @ W2[128,128] + b2
// Block: 64 tokens, 256 threads. Register tile 8 tokens x 4 cols per thread.
// ---------------------------------------------------------------------------
__global__ __launch_bounds__(256) void enc_kernel(
    const float* __restrict__ x,
    const float* __restrict__ w1, const float* __restrict__ b1,
    const float* __restrict__ w2, const float* __restrict__ b2,
    float* __restrict__ out)
{
    extern __shared__ float sm[];
    float* W1s = sm;            // 6*128 = 768
    float* B1s = W1s + 768;     // 128
    float* B2s = B1s + 128;     // 128
    float* W2s = B2s + 128;     // 128*128 = 16384
    float* XS  = W2s + 16384;   // 64*6 = 384
    float* H1s = XS + 384;      // 64*128 = 8192

    const int tid = threadIdx.x;
    const int token0 = blockIdx.x * TILE;

    for (int i = tid; i < 768; i += 256) W1s[i] = w1[i];
    if (tid < 128) { B1s[tid] = b1[tid]; B2s[tid] = b2[tid]; }
    {
        const float4* w24 = (const float4*)w2;
        float4* W2s4 = (float4*)W2s;
        for (int i = tid; i < 4096; i += 256) W2s4[i] = w24[i];
    }
    for (int i = tid; i < TILE*6; i += 256) XS[i] = x[token0*6 + i];
    __syncthreads();

    const int rg = tid >> 5;    // row group 0..7 (8 tokens each)
    const int ct = tid & 31;    // col thread (4 cols each)

    // First linear + ReLU into smem
    #pragma unroll
    for (int t = 0; t < 8; t++) {
        const int row = rg*8 + t;
        #pragma unroll
        for (int cc = 0; cc < 4; cc++) {
            const int c = ct*4 + cc;
            float a = B1s[c];
            #pragma unroll
            for (int k = 0; k < 6; k++) a += XS[row*6+k] * W1s[k*128+c];
            H1s[row*128 + c] = fmaxf(a, 0.f);
        }
    }
    __syncthreads();

    // Second linear (no relu)
    float4 acc[8];
    #pragma unroll
    for (int t = 0; t < 8; t++) {
        acc[t].x = B2s[ct*4+0]; acc[t].y = B2s[ct*4+1];
        acc[t].z = B2s[ct*4+2]; acc[t].w = B2s[ct*4+3];
    }
    const float4* W2s4 = (const float4*)W2s;
    #pragma unroll 8
    for (int k = 0; k < 128; k++) {
        const float4 w = W2s4[k*32 + ct];
        #pragma unroll
        for (int t = 0; t < 8; t++) {
            const float hv = H1s[(rg*8+t)*128 + k];
            acc[t].x += hv*w.x; acc[t].y += hv*w.y;
            acc[t].z += hv*w.z; acc[t].w += hv*w.w;
        }
    }
    float4* o4 = (float4*)out;
    #pragma unroll
    for (int t = 0; t < 8; t++)
        o4[(size_t)(token0 + rg*8 + t)*32 + ct] = acc[t];
}

// ---------------------------------------------------------------------------
// GC stage: out = relu( band_agg(h) @ W + b )   [uses linearity of band_agg]
// Block: 64 output tokens; loads 66-row halo tile, aggregates in smem, GEMM.
// ---------------------------------------------------------------------------
__global__ __launch_bounds__(256) void gc_kernel(
    const float* __restrict__ h,
    const float* __restrict__ w, const float* __restrict__ bias,
    float* __restrict__ out)
{
    extern __shared__ float sm[];
    float* Ws  = sm;              // 16384
    float* Bs  = Ws + 16384;      // 128
    float* RAW = Bs + 128;        // 66*128 = 8448
    float* AG  = RAW + 8448;      // 64*128 = 8192

    const int tid = threadIdx.x;
    const int token0 = blockIdx.x * TILE;
    const int s0 = token0 & (SEQ-1);
    const int batch_base = token0 - s0;

    {
        const float4* w4 = (const float4*)w;
        float4* Ws4 = (float4*)Ws;
        for (int i = tid; i < 4096; i += 256) Ws4[i] = w4[i];
    }
    if (tid < 128) Bs[tid] = bias[tid];
    {
        float4* R4 = (float4*)RAW;
        const float4* h4 = (const float4*)h;
        for (int idx = tid; idx < 66*32; idx += 256) {
            const int i = idx >> 5, c = idx & 31;
            const int s = s0 - 1 + i;
            float4 v = make_float4(0.f, 0.f, 0.f, 0.f);
            if (s >= 0 && s < SEQ) v = h4[(size_t)(batch_base + s)*32 + c];
            R4[i*32 + c] = v;
        }
    }
    __syncthreads();
    {
        float4* A4 = (float4*)AG;
        const float4* R4 = (const float4*)RAW;
        for (int idx = tid; idx < 64*32; idx += 256) {
            const int i = idx >> 5, c = idx & 31;
            const int s = s0 + i;
            const float r = (s == 0 || s == SEQ-1) ? (1.f/2.f) : (1.f/3.f);
            const float4 a = R4[i*32+c], b4 = R4[(i+1)*32+c], c4 = R4[(i+2)*32+c];
            A4[idx] = make_float4((a.x+b4.x+c4.x)*r, (a.y+b4.y+c4.y)*r,
                                  (a.z+b4.z+c4.z)*r, (a.w+b4.w+c4.w)*r);
        }
    }
    __syncthreads();

    const int rg = tid >> 5, ct = tid & 31;
    float4 acc[8];
    #pragma unroll
    for (int t = 0; t < 8; t++) {
        acc[t].x = Bs[ct*4+0]; acc[t].y = Bs[ct*4+1];
        acc[t].z = Bs[ct*4+2]; acc[t].w = Bs[ct*4+3];
    }
    const float4* Ws4 = (const float4*)Ws;
    #pragma unroll 8
    for (int k = 0; k < 128; k++) {
        const float4 wv = Ws4[k*32 + ct];
        #pragma unroll
        for (int t = 0; t < 8; t++) {
            const float hv = AG[(rg*8+t)*128 + k];
            acc[t].x += hv*wv.x; acc[t].y += hv*wv.y;
            acc[t].z += hv*wv.z; acc[t].w += hv*wv.w;
        }
    }
    float4* o4 = (float4*)out;
    #pragma unroll
    for (int t = 0; t < 8; t++) {
        float4 v = acc[t];
        v.x = fmaxf(v.x, 0.f); v.y = fmaxf(v.y, 0.f);
        v.z = fmaxf(v.z, 0.f); v.w = fmaxf(v.w, 0.f);
        o4[(size_t)(token0 + rg*8 + t)*32 + ct] = v;
    }
}

// ---------------------------------------------------------------------------
// Pool partials: 8 blocks per batch, each sums 256 rows
// ---------------------------------------------------------------------------
__global__ __launch_bounds__(128) void pool_part_kernel(const float* __restrict__ h)
{
    const int b = blockIdx.x >> 3, j = blockIdx.x & 7;
    const int tid = threadIdx.x;
    const float* base = h + ((size_t)b*SEQ + j*256)*DIM;
    float s = 0.f;
    #pragma unroll 8
    for (int r = 0; r < 256; r++) s += base[(size_t)r*DIM + tid];
    g_part[blockIdx.x*DIM + tid] = s;
}

// ---------------------------------------------------------------------------
// Final: pooled mean -> relu(pooled@W1+b1) @ W2 + b2
// ---------------------------------------------------------------------------
__global__ __launch_bounds__(128) void cls_kernel(
    const float* __restrict__ w1, const float* __restrict__ b1,
    const float* __restrict__ w2, const float* __restrict__ b2,
    float* __restrict__ out)
{
    __shared__ float P[128];
    __shared__ float C1[64];
    const int b = blockIdx.x, tid = threadIdx.x;
    float s = 0.f;
    #pragma unroll
    for (int j = 0; j < 8; j++) s += g_part[(b*8+j)*DIM + tid];
    P[tid] = s * (1.0f/(float)SEQ);
    __syncthreads();
    if (tid < 64) {
        float a = b1[tid];
        #pragma unroll 8
        for (int k = 0; k < 128; k++) a += P[k] * w1[k*64 + tid];
        C1[tid] = fmaxf(a, 0.f);
    }
    __syncthreads();
    if (tid < 3) {
        float a = b2[tid];
        #pragma unroll
        for (int k = 0; k < 64; k++) a += C1[k] * w2[k*3 + tid];
        out[b*3 + tid] = a;
    }
}

extern "C" void kernel_launch(void* const* d_in, const int* in_sizes, int n_in,
                              void* d_out, int out_size)
{
    const float* x      = (const float*)d_in[0];
    const float* enc_w1 = (const float*)d_in[1];
    const float* enc_b1 = (const float*)d_in[2];
    const float* enc_w2 = (const float*)d_in[3];
    const float* enc_b2 = (const float*)d_in[4];
    const float* gc1_w  = (const float*)d_in[5];
    const float* gc1_b  = (const float*)d_in[6];
    const float* gc2_w  = (const float*)d_in[7];
    const float* gc2_b  = (const float*)d_in[8];
    const float* gc3_w  = (const float*)d_in[9];
    const float* gc3_b  = (const float*)d_in[10];
    const float* cls_w1 = (const float*)d_in[11];
    const float* cls_b1 = (const float*)d_in[12];
    const float* cls_w2 = (const float*)d_in[13];
    const float* cls_b2 = (const float*)d_in[14];
    float* out = (float*)d_out;

    const size_t enc_sm = (size_t)(768+128+128+16384+384+8192) * sizeof(float);
    const size_t gc_sm  = (size_t)(16384+128+8448+8192) * sizeof(float);
    cudaFuncSetAttribute(enc_kernel, cudaFuncAttributeMaxDynamicSharedMemorySize, (int)enc_sm);
    cudaFuncSetAttribute(gc_kernel,  cudaFuncAttributeMaxDynamicSharedMemorySize, (int)gc_sm);

    void* p0; void* p1;
    cudaGetSymbolAddress(&p0, g_h0);
    cudaGetSymbolAddress(&p1, g_h1);
    float* h0 = (float*)p0;
    float* h1 = (float*)p1;

    const int nblk = NTOK / TILE;  // 1024
    enc_kernel<<<nblk, 256, enc_sm>>>(x, enc_w1, enc_b1, enc_w2, enc_b2, h0);
    gc_kernel<<<nblk, 256, gc_sm>>>(h0, gc1_w, gc1_b, h1);
    gc_kernel<<<nblk, 256, gc_sm>>>(h1, gc2_w, gc2_b, h0);
    gc_kernel<<<nblk, 256, gc_sm>>>(h0, gc3_w, gc3_b, h1);
    pool_part_kernel<<<NB*8, 128>>>(h1);
    cls_kernel<<<NB, 128>>>(cls_w1, cls_b1, cls_w2, cls_b2, out);
}

// round 3
// speedup vs baseline: 1.4246x; 1.4246x over previous
#include <cuda_runtime.h>
#include <cuda_bf16.h>
#include <cstdint>

#define SEQ 2048
#define NB  32
#define DIM 128
#define NTOK (NB*SEQ)

// row stride for smem tiles: 136 bf16 = 272 bytes (16B aligned rows, conflict-free frags)
#define RS 136
#define RSB (RS*2)

// ---------------- scratch (no allocations allowed) ----------------
__device__ float g_h0[NTOK*DIM];
__device__ float g_h1[NTOK*DIM];
__device__ float g_part[NB*8*DIM];
// prepared weight images: bf16 hi/lo, [n][k] row-major, unpadded
__device__ __align__(16) __nv_bfloat16 g_Bhi[4][DIM*DIM];
__device__ __align__(16) __nv_bfloat16 g_Blo[4][DIM*DIM];

// ---------------- helpers ----------------
__device__ __forceinline__ uint32_t smem_u32(const void* p) {
    uint32_t a;
    asm("{ .reg .u64 t; cvta.to.shared.u64 t, %1; cvt.u32.u64 %0, t; }" : "=r"(a) : "l"(p));
    return a;
}
__device__ __forceinline__ void sts128(uint32_t addr, uint4 v) {
    asm volatile("st.shared.v4.b32 [%0], {%1,%2,%3,%4};" :: "r"(addr), "r"(v.x), "r"(v.y), "r"(v.z), "r"(v.w) : "memory");
}
__device__ __forceinline__ uint32_t lds32(uint32_t a) {
    uint32_t v;
    asm("ld.shared.b32 %0, [%1];" : "=r"(v) : "r"(a));
    return v;
}
__device__ __forceinline__ void mma16816(float* d, const uint32_t* a, const uint32_t* b) {
    asm volatile(
        "mma.sync.aligned.m16n8k16.row.col.f32.bf16.bf16.f32 "
        "{%0,%1,%2,%3}, {%4,%5,%6,%7}, {%8,%9}, {%0,%1,%2,%3};"
        : "+f"(d[0]), "+f"(d[1]), "+f"(d[2]), "+f"(d[3])
        : "r"(a[0]), "r"(a[1]), "r"(a[2]), "r"(a[3]), "r"(b[0]), "r"(b[1]));
}
__device__ __forceinline__ uint32_t packbf(float a, float b) {
    __nv_bfloat162 t = __floats2bfloat162_rn(a, b);
    return *reinterpret_cast<uint32_t*>(&t);
}

// ---------------------------------------------------------------------------
// Weight prep: fp32 [k][n] -> bf16 hi/lo, transposed to [n][k] row-major
// ---------------------------------------------------------------------------
__global__ void prep_w(const float* __restrict__ w0, const float* __restrict__ w1,
                       const float* __restrict__ w2, const float* __restrict__ w3)
{
    const float* ws[4] = {w0, w1, w2, w3};
    const float* w = ws[blockIdx.x];
    char* bh = (char*)g_Bhi[blockIdx.x];
    char* bl = (char*)g_Blo[blockIdx.x];
    for (int c = threadIdx.x; c < DIM * DIM / 8; c += blockDim.x) {
        const int n = c >> 4;
        const int k0 = (c & 15) * 8;
        float v[8], lf[8];
        #pragma unroll
        for (int j = 0; j < 8; j++) v[j] = w[(k0 + j) * DIM + n];
        #pragma unroll
        for (int j = 0; j < 8; j++)
            lf[j] = v[j] - __bfloat162float(__float2bfloat16_rn(v[j]));
        uint4 hp, lp;
        hp.x = packbf(v[0], v[1]); hp.y = packbf(v[2], v[3]);
        hp.z = packbf(v[4], v[5]); hp.w = packbf(v[6], v[7]);
        lp.x = packbf(lf[0], lf[1]); lp.y = packbf(lf[2], lf[3]);
        lp.z = packbf(lf[4], lf[5]); lp.w = packbf(lf[6], lf[7]);
        const uint32_t off = (uint32_t)(n * DIM + k0) * 2;
        *(uint4*)(bh + off) = hp;
        *(uint4*)(bl + off) = lp;
    }
}

// ---------------------------------------------------------------------------
// Stage kernel: build A (enc layer1 or band_agg) as bf16 hi/lo in smem,
// then 3-product split GEMM on mma.sync bf16, bias(+relu) epilogue.
// mode 0 = encoder (in = x), mode 1 = gc (band_agg + relu)
// ---------------------------------------------------------------------------
__global__ __launch_bounds__(256, 1)
void stage_kernel(const float* __restrict__ in,
                  const __nv_bfloat16* __restrict__ Bhi_g,
                  const __nv_bfloat16* __restrict__ Blo_g,
                  const float* __restrict__ bias,
                  const float* __restrict__ w1, const float* __restrict__ b1,
                  float* __restrict__ out, int mode)
{
    extern __shared__ float sm[];
    const int tid = threadIdx.x;
    const int wid = tid >> 5, lid = tid & 31;
    const uint32_t smb = smem_u32(sm);
    // header: bias[128] | w1[768] | b1[128] -> 1024 floats = 4KB
    const uint32_t AhiS = smb + 4096;
    const uint32_t AloS = AhiS + DIM * RSB;      // +34816
    const uint32_t BhiS = AloS + DIM * RSB;
    const uint32_t BloS = BhiS + DIM * RSB;
    const int token0 = blockIdx.x * 128;

    if (tid < 128) sm[tid] = bias[tid];
    if (mode == 0) {
        for (int i = tid; i < 768; i += 256) sm[128 + i] = w1[i];
        if (tid < 128) sm[896 + tid] = b1[tid];
    }
    // copy prepared weight images into padded smem tiles
    {
        const uint4* sh = (const uint4*)Bhi_g;
        const uint4* sl = (const uint4*)Blo_g;
        for (int i = tid; i < 2048; i += 256) {
            const uint32_t dst = (uint32_t)((i >> 4) * RSB + (i & 15) * 16);
            sts128(BhiS + dst, sh[i]);
            sts128(BloS + dst, sl[i]);
        }
    }

    // -------- build A (hi/lo) --------
    const int row = tid >> 1, half = tid & 1;
    if (mode == 1) {
        const int s = (token0 & (SEQ - 1)) + row;
        const float scale = (s == 0 || s == SEQ - 1) ? 0.5f : (1.0f / 3.0f);
        const float4* pc = (const float4*)(in + (size_t)(token0 + row) * DIM + half * 64);
        const bool hl = (s > 0), hr = (s < SEQ - 1);
        #pragma unroll
        for (int ch = 0; ch < 8; ch++) {
            float4 c0 = pc[ch * 2], c1 = pc[ch * 2 + 1];
            float4 z = make_float4(0.f, 0.f, 0.f, 0.f);
            float4 l0 = z, l1 = z, r0 = z, r1 = z;
            if (hl) { l0 = pc[ch * 2 - 32]; l1 = pc[ch * 2 + 1 - 32]; }
            if (hr) { r0 = pc[ch * 2 + 32]; r1 = pc[ch * 2 + 1 + 32]; }
            float v[8], lf[8];
            v[0] = (c0.x + l0.x + r0.x) * scale; v[1] = (c0.y + l0.y + r0.y) * scale;
            v[2] = (c0.z + l0.z + r0.z) * scale; v[3] = (c0.w + l0.w + r0.w) * scale;
            v[4] = (c1.x + l1.x + r1.x) * scale; v[5] = (c1.y + l1.y + r1.y) * scale;
            v[6] = (c1.z + l1.z + r1.z) * scale; v[7] = (c1.w + l1.w + r1.w) * scale;
            #pragma unroll
            for (int j = 0; j < 8; j++)
                lf[j] = v[j] - __bfloat162float(__float2bfloat16_rn(v[j]));
            uint4 hp, lp;
            hp.x = packbf(v[0], v[1]); hp.y = packbf(v[2], v[3]);
            hp.z = packbf(v[4], v[5]); hp.w = packbf(v[6], v[7]);
            lp.x = packbf(lf[0], lf[1]); lp.y = packbf(lf[2], lf[3]);
            lp.z = packbf(lf[4], lf[5]); lp.w = packbf(lf[6], lf[7]);
            const int k0 = half * 64 + ch * 8;
            const uint32_t off = (uint32_t)(row * RSB + k0 * 2);
            sts128(AhiS + off, hp);
            sts128(AloS + off, lp);
        }
    } else {
        float xv[6];
        const float* xr = in + (size_t)(token0 + row) * 6;
        #pragma unroll
        for (int k = 0; k < 6; k++) xv[k] = xr[k];
        __syncthreads();   // w1/b1 header must be ready
        #pragma unroll
        for (int ch = 0; ch < 8; ch++) {
            const int k0 = half * 64 + ch * 8;
            float v[8], lf[8];
            #pragma unroll
            for (int j = 0; j < 8; j++) {
                const int c = k0 + j;
                float a = sm[896 + c];
                #pragma unroll
                for (int k = 0; k < 6; k++) a += xv[k] * sm[128 + k * 128 + c];
                v[j] = fmaxf(a, 0.f);
                lf[j] = v[j] - __bfloat162float(__float2bfloat16_rn(v[j]));
            }
            uint4 hp, lp;
            hp.x = packbf(v[0], v[1]); hp.y = packbf(v[2], v[3]);
            hp.z = packbf(v[4], v[5]); hp.w = packbf(v[6], v[7]);
            lp.x = packbf(lf[0], lf[1]); lp.y = packbf(lf[2], lf[3]);
            lp.z = packbf(lf[4], lf[5]); lp.w = packbf(lf[6], lf[7]);
            const uint32_t off = (uint32_t)(row * RSB + k0 * 2);
            sts128(AhiS + off, hp);
            sts128(AloS + off, lp);
        }
    }
    __syncthreads();

    // -------- warp-level split GEMM: warp (wm, wn) owns rows wm*32+, cols wn*64+ --------
    const int wm = wid & 3, wn = wid >> 2;
    const int g = lid >> 2, t = lid & 3;

    float acc[2][8][4];
    #pragma unroll
    for (int mi = 0; mi < 2; mi++)
        #pragma unroll
        for (int ni = 0; ni < 8; ni++)
            #pragma unroll
            for (int j = 0; j < 4; j++) acc[mi][ni][j] = 0.f;

    const uint32_t aoff = (uint32_t)((wm * 32 + g) * RSB + 4 * t);
    const uint32_t boff = (uint32_t)((wn * 64 + g) * RSB + 4 * t);

    #pragma unroll
    for (int ks = 0; ks < 8; ks++) {
        const uint32_t kb = ks * 32;  // 16 bf16 = 32B per kstep
        uint32_t ah[2][4], al[2][4];
        #pragma unroll
        for (int mi = 0; mi < 2; mi++) {
            const uint32_t r0 = AhiS + aoff + mi * 16 * RSB + kb;
            ah[mi][0] = lds32(r0);
            ah[mi][1] = lds32(r0 + 8 * RSB);
            ah[mi][2] = lds32(r0 + 16);
            ah[mi][3] = lds32(r0 + 8 * RSB + 16);
            const uint32_t r1 = AloS + aoff + mi * 16 * RSB + kb;
            al[mi][0] = lds32(r1);
            al[mi][1] = lds32(r1 + 8 * RSB);
            al[mi][2] = lds32(r1 + 16);
            al[mi][3] = lds32(r1 + 8 * RSB + 16);
        }
        #pragma unroll
        for (int ni = 0; ni < 8; ni++) {
            uint32_t bh[2], bl[2];
            const uint32_t rb = BhiS + boff + ni * 8 * RSB + kb;
            bh[0] = lds32(rb); bh[1] = lds32(rb + 16);
            const uint32_t rl = BloS + boff + ni * 8 * RSB + kb;
            bl[0] = lds32(rl); bl[1] = lds32(rl + 16);
            #pragma unroll
            for (int mi = 0; mi < 2; mi++) {
                mma16816(acc[mi][ni], ah[mi], bh);
                mma16816(acc[mi][ni], al[mi], bh);
                mma16816(acc[mi][ni], ah[mi], bl);
            }
        }
    }

    // -------- epilogue: bias (+relu), float2 stores --------
    const bool relu = (mode == 1);
    #pragma unroll
    for (int mi = 0; mi < 2; mi++) {
        const int r0 = token0 + wm * 32 + mi * 16 + g;
        #pragma unroll
        for (int ni = 0; ni < 8; ni++) {
            const int col = wn * 64 + ni * 8 + 2 * t;
            const float bx = sm[col], by = sm[col + 1];
            float2 v0, v1;
            v0.x = acc[mi][ni][0] + bx; v0.y = acc[mi][ni][1] + by;
            v1.x = acc[mi][ni][2] + bx; v1.y = acc[mi][ni][3] + by;
            if (relu) {
                v0.x = fmaxf(v0.x, 0.f); v0.y = fmaxf(v0.y, 0.f);
                v1.x = fmaxf(v1.x, 0.f); v1.y = fmaxf(v1.y, 0.f);
            }
            *(float2*)(out + (size_t)r0 * DIM + col) = v0;
            *(float2*)(out + (size_t)(r0 + 8) * DIM + col) = v1;
        }
    }
}

// ---------------------------------------------------------------------------
// Pool partials + classifier
// ---------------------------------------------------------------------------
__global__ __launch_bounds__(128) void pool_part_kernel(const float* __restrict__ h)
{
    const int b = blockIdx.x >> 3, j = blockIdx.x & 7;
    const int tid = threadIdx.x;
    const float* base = h + ((size_t)b * SEQ + j * 256) * DIM;
    float s = 0.f;
    #pragma unroll 8
    for (int r = 0; r < 256; r++) s += base[(size_t)r * DIM + tid];
    g_part[blockIdx.x * DIM + tid] = s;
}

__global__ __launch_bounds__(128) void cls_kernel(
    const float* __restrict__ w1, const float* __restrict__ b1,
    const float* __restrict__ w2, const float* __restrict__ b2,
    float* __restrict__ out)
{
    __shared__ float P[128];
    __shared__ float C1[64];
    const int b = blockIdx.x, tid = threadIdx.x;
    float s = 0.f;
    #pragma unroll
    for (int j = 0; j < 8; j++) s += g_part[(b * 8 + j) * DIM + tid];
    P[tid] = s * (1.0f / (float)SEQ);
    __syncthreads();
    if (tid < 64) {
        float a = b1[tid];
        #pragma unroll 8
        for (int k = 0; k < 128; k++) a += P[k] * w1[k * 64 + tid];
        C1[tid] = fmaxf(a, 0.f);
    }
    __syncthreads();
    if (tid < 3) {
        float a = b2[tid];
        #pragma unroll
        for (int k = 0; k < 64; k++) a += C1[k] * w2[k * 3 + tid];
        out[b * 3 + tid] = a;
    }
}

extern "C" void kernel_launch(void* const* d_in, const int* in_sizes, int n_in,
                              void* d_out, int out_size)
{
    const float* x      = (const float*)d_in[0];
    const float* enc_w1 = (const float*)d_in[1];
    const float* enc_b1 = (const float*)d_in[2];
    const float* enc_w2 = (const float*)d_in[3];
    const float* enc_b2 = (const float*)d_in[4];
    const float* gc1_w  = (const float*)d_in[5];
    const float* gc1_b  = (const float*)d_in[6];
    const float* gc2_w  = (const float*)d_in[7];
    const float* gc2_b  = (const float*)d_in[8];
    const float* gc3_w  = (const float*)d_in[9];
    const float* gc3_b  = (const float*)d_in[10];
    const float* cls_w1 = (const float*)d_in[11];
    const float* cls_b1 = (const float*)d_in[12];
    const float* cls_w2 = (const float*)d_in[13];
    const float* cls_b2 = (const float*)d_in[14];
    float* out = (float*)d_out;

    void *p0, *p1, *pbh, *pbl;
    cudaGetSymbolAddress(&p0, g_h0);
    cudaGetSymbolAddress(&p1, g_h1);
    cudaGetSymbolAddress(&pbh, g_Bhi);
    cudaGetSymbolAddress(&pbl, g_Blo);
    float* h0 = (float*)p0;
    float* h1 = (float*)p1;
    const __nv_bfloat16* Bhi = (const __nv_bfloat16*)pbh;
    const __nv_bfloat16* Blo = (const __nv_bfloat16*)pbl;

    const size_t stage_sm = 4096 + 4 * (size_t)DIM * RSB;   // 4KB header + 4 padded tiles
    cudaFuncSetAttribute(stage_kernel, cudaFuncAttributeMaxDynamicSharedMemorySize, (int)stage_sm);

    prep_w<<<4, 256>>>(enc_w2, gc1_w, gc2_w, gc3_w);

    const int nblk = NTOK / 128;   // 512
    stage_kernel<<<nblk, 256, stage_sm>>>(x,  Bhi + 0 * DIM * DIM, Blo + 0 * DIM * DIM, enc_b2, enc_w1, enc_b1, h0, 0);
    stage_kernel<<<nblk, 256, stage_sm>>>(h0, Bhi + 1 * DIM * DIM, Blo + 1 * DIM * DIM, gc1_b,  enc_w1, enc_b1, h1, 1);
    stage_kernel<<<nblk, 256, stage_sm>>>(h1, Bhi + 2 * DIM * DIM, Blo + 2 * DIM * DIM, gc2_b,  enc_w1, enc_b1, h0, 1);
    stage_kernel<<<nblk, 256, stage_sm>>>(h0, Bhi + 3 * DIM * DIM, Blo + 3 * DIM * DIM, gc3_b,  enc_w1, enc_b1, h1, 1);
    pool_part_kernel<<<NB * 8, 128>>>(h1);
    cls_kernel<<<NB, 128>>>(cls_w1, cls_b1, cls_w2, cls_b2, out);
}

// round 4
// speedup vs baseline: 1.4548x; 1.0212x over previous
#include <cuda_runtime.h>
#include <cuda_bf16.h>
#include <cstdint>

#define SEQ 2048
#define NB  32
#define DIM 128
#define NTOK (NB*SEQ)

// row stride for smem tiles: 136 bf16 = 272 bytes (16B aligned rows, conflict-free)
#define RS 136
#define RSB (RS*2)

// ---------------- scratch (no allocations allowed) ----------------
__device__ float g_h0[NTOK*DIM];
__device__ float g_h1[NTOK*DIM];
__device__ float g_part[NB*8*DIM];
// prepared weight images: bf16 hi/lo, [n][k] row-major, unpadded
__device__ __align__(16) __nv_bfloat16 g_Bhi[4][DIM*DIM];
__device__ __align__(16) __nv_bfloat16 g_Blo[4][DIM*DIM];

// ---------------- helpers ----------------
__device__ __forceinline__ uint32_t smem_u32(const void* p) {
    uint32_t a;
    asm("{ .reg .u64 t; cvta.to.shared.u64 t, %1; cvt.u32.u64 %0, t; }" : "=r"(a) : "l"(p));
    return a;
}
__device__ __forceinline__ void sts128(uint32_t addr, uint4 v) {
    asm volatile("st.shared.v4.b32 [%0], {%1,%2,%3,%4};" :: "r"(addr), "r"(v.x), "r"(v.y), "r"(v.z), "r"(v.w) : "memory");
}
#define LDMX4(r, addr) \
    asm volatile("ldmatrix.sync.aligned.m8n8.x4.shared.b16 {%0,%1,%2,%3}, [%4];" \
        : "=r"((r)[0]), "=r"((r)[1]), "=r"((r)[2]), "=r"((r)[3]) : "r"(addr))
__device__ __forceinline__ void mma16816(float* d, const uint32_t* a, const uint32_t* b) {
    asm volatile(
        "mma.sync.aligned.m16n8k16.row.col.f32.bf16.bf16.f32 "
        "{%0,%1,%2,%3}, {%4,%5,%6,%7}, {%8,%9}, {%0,%1,%2,%3};"
        : "+f"(d[0]), "+f"(d[1]), "+f"(d[2]), "+f"(d[3])
        : "r"(a[0]), "r"(a[1]), "r"(a[2]), "r"(a[3]), "r"(b[0]), "r"(b[1]));
}
__device__ __forceinline__ uint32_t packbf(float a, float b) {
    __nv_bfloat162 t = __floats2bfloat162_rn(a, b);
    return *reinterpret_cast<uint32_t*>(&t);
}

// ---------------------------------------------------------------------------
// Weight prep: fp32 [k][n] -> bf16 hi/lo, transposed to [n][k] row-major
// ---------------------------------------------------------------------------
__global__ void prep_w(const float* __restrict__ w0, const float* __restrict__ w1,
                       const float* __restrict__ w2, const float* __restrict__ w3)
{
    const float* ws[4] = {w0, w1, w2, w3};
    const float* w = ws[blockIdx.x];
    char* bh = (char*)g_Bhi[blockIdx.x];
    char* bl = (char*)g_Blo[blockIdx.x];
    for (int c = threadIdx.x; c < DIM * DIM / 8; c += blockDim.x) {
        const int n = c >> 4;
        const int k0 = (c & 15) * 8;
        float v[8], lf[8];
        #pragma unroll
        for (int j = 0; j < 8; j++) v[j] = w[(k0 + j) * DIM + n];
        #pragma unroll
        for (int j = 0; j < 8; j++)
            lf[j] = v[j] - __bfloat162float(__float2bfloat16_rn(v[j]));
        uint4 hp, lp;
        hp.x = packbf(v[0], v[1]); hp.y = packbf(v[2], v[3]);
        hp.z = packbf(v[4], v[5]); hp.w = packbf(v[6], v[7]);
        lp.x = packbf(lf[0], lf[1]); lp.y = packbf(lf[2], lf[3]);
        lp.z = packbf(lf[4], lf[5]); lp.w = packbf(lf[6], lf[7]);
        const uint32_t off = (uint32_t)(n * DIM + k0) * 2;
        *(uint4*)(bh + off) = hp;
        *(uint4*)(bl + off) = lp;
    }
}

// ---------------------------------------------------------------------------
// Stage kernel: build A (enc layer1 or band_agg) as bf16 hi/lo in smem,
// then 3-product split GEMM with ldmatrix fragment loads.
// mode 0 = encoder (in = x), mode 1 = gc (band_agg + relu)
// ---------------------------------------------------------------------------
__global__ __launch_bounds__(256, 1)
void stage_kernel(const float* __restrict__ in,
                  const __nv_bfloat16* __restrict__ Bhi_g,
                  const __nv_bfloat16* __restrict__ Blo_g,
                  const float* __restrict__ bias,
                  const float* __restrict__ w1, const float* __restrict__ b1,
                  float* __restrict__ out, int mode)
{
    extern __shared__ float sm[];
    const int tid = threadIdx.x;
    const int wid = tid >> 5, lid = tid & 31;
    const uint32_t smb = smem_u32(sm);
    const uint32_t AhiS = smb + 4096;
    const uint32_t AloS = AhiS + DIM * RSB;
    const uint32_t BhiS = AloS + DIM * RSB;
    const uint32_t BloS = BhiS + DIM * RSB;
    const int token0 = blockIdx.x * 128;

    if (tid < 128) sm[tid] = bias[tid];
    if (mode == 0) {
        for (int i = tid; i < 768; i += 256) sm[128 + i] = w1[i];
        if (tid < 128) sm[896 + tid] = b1[tid];
    }
    {
        const uint4* sh = (const uint4*)Bhi_g;
        const uint4* sl = (const uint4*)Blo_g;
        for (int i = tid; i < 2048; i += 256) {
            const uint32_t dst = (uint32_t)((i >> 4) * RSB + (i & 15) * 16);
            sts128(BhiS + dst, sh[i]);
            sts128(BloS + dst, sl[i]);
        }
    }

    // -------- build A (hi/lo) --------
    const int row = tid >> 1, half = tid & 1;
    if (mode == 1) {
        const int s = (token0 & (SEQ - 1)) + row;
        const float scale = (s == 0 || s == SEQ - 1) ? 0.5f : (1.0f / 3.0f);
        const float4* pc = (const float4*)(in + (size_t)(token0 + row) * DIM + half * 64);
        const bool hl = (s > 0), hr = (s < SEQ - 1);
        #pragma unroll
        for (int ch = 0; ch < 8; ch++) {
            float4 c0 = pc[ch * 2], c1 = pc[ch * 2 + 1];
            float4 z = make_float4(0.f, 0.f, 0.f, 0.f);
            float4 l0 = z, l1 = z, r0 = z, r1 = z;
            if (hl) { l0 = pc[ch * 2 - 32]; l1 = pc[ch * 2 + 1 - 32]; }
            if (hr) { r0 = pc[ch * 2 + 32]; r1 = pc[ch * 2 + 1 + 32]; }
            float v[8], lf[8];
            v[0] = (c0.x + l0.x + r0.x) * scale; v[1] = (c0.y + l0.y + r0.y) * scale;
            v[2] = (c0.z + l0.z + r0.z) * scale; v[3] = (c0.w + l0.w + r0.w) * scale;
            v[4] = (c1.x + l1.x + r1.x) * scale; v[5] = (c1.y + l1.y + r1.y) * scale;
            v[6] = (c1.z + l1.z + r1.z) * scale; v[7] = (c1.w + l1.w + r1.w) * scale;
            #pragma unroll
            for (int j = 0; j < 8; j++)
                lf[j] = v[j] - __bfloat162float(__float2bfloat16_rn(v[j]));
            uint4 hp, lp;
            hp.x = packbf(v[0], v[1]); hp.y = packbf(v[2], v[3]);
            hp.z = packbf(v[4], v[5]); hp.w = packbf(v[6], v[7]);
            lp.x = packbf(lf[0], lf[1]); lp.y = packbf(lf[2], lf[3]);
            lp.z = packbf(lf[4], lf[5]); lp.w = packbf(lf[6], lf[7]);
            const int k0 = half * 64 + ch * 8;
            const uint32_t off = (uint32_t)(row * RSB + k0 * 2);
            sts128(AhiS + off, hp);
            sts128(AloS + off, lp);
        }
    } else {
        float xv[6];
        const float* xr = in + (size_t)(token0 + row) * 6;
        #pragma unroll
        for (int k = 0; k < 6; k++) xv[k] = xr[k];
        __syncthreads();   // w1/b1 header must be ready
        #pragma unroll
        for (int ch = 0; ch < 8; ch++) {
            const int k0 = half * 64 + ch * 8;
            float v[8], lf[8];
            #pragma unroll
            for (int j = 0; j < 8; j++) {
                const int c = k0 + j;
                float a = sm[896 + c];
                #pragma unroll
                for (int k = 0; k < 6; k++) a += xv[k] * sm[128 + k * 128 + c];
                v[j] = fmaxf(a, 0.f);
                lf[j] = v[j] - __bfloat162float(__float2bfloat16_rn(v[j]));
            }
            uint4 hp, lp;
            hp.x = packbf(v[0], v[1]); hp.y = packbf(v[2], v[3]);
            hp.z = packbf(v[4], v[5]); hp.w = packbf(v[6], v[7]);
            lp.x = packbf(lf[0], lf[1]); lp.y = packbf(lf[2], lf[3]);
            lp.z = packbf(lf[4], lf[5]); lp.w = packbf(lf[6], lf[7]);
            const uint32_t off = (uint32_t)(row * RSB + k0 * 2);
            sts128(AhiS + off, hp);
            sts128(AloS + off, lp);
        }
    }
    __syncthreads();

    // -------- warp-level split GEMM with ldmatrix fragment loads --------
    const int wm = wid & 3, wn = wid >> 2;
    const int g = lid >> 2, t = lid & 3;

    float acc[2][8][4];
    #pragma unroll
    for (int mi = 0; mi < 2; mi++)
        #pragma unroll
        for (int ni = 0; ni < 8; ni++)
            #pragma unroll
            for (int j = 0; j < 4; j++) acc[mi][ni][j] = 0.f;

    // per-lane ldmatrix source offsets
    // A x4: m0 rows0-7@k0 | m1 rows8-15@k0 | m2 rows0-7@k+8 | m3 rows8-15@k+8
    const uint32_t aoffl = (uint32_t)((((lid >> 3) & 1) * 8 + (lid & 7)) * RSB + (lid >> 4) * 16);
    // B x4: m0 n0-7@k0 | m1 n0-7@k+8 | m2 n8-15@k0 | m3 n8-15@k+8
    const uint32_t boffl = (uint32_t)((((lid >> 4) * 8) + (lid & 7)) * RSB + ((lid >> 3) & 1) * 16);

    const uint32_t aBase = (uint32_t)(wm * 32) * RSB + aoffl;
    const uint32_t bBase = (uint32_t)(wn * 64) * RSB + boffl;

    #pragma unroll
    for (int ks = 0; ks < 8; ks++) {
        const uint32_t kb = ks * 32;  // 16 bf16 = 32B per kstep
        uint32_t ah[2][4], al[2][4];
        LDMX4(ah[0], AhiS + aBase + kb);
        LDMX4(ah[1], AhiS + aBase + 16 * RSB + kb);
        LDMX4(al[0], AloS + aBase + kb);
        LDMX4(al[1], AloS + aBase + 16 * RSB + kb);
        uint32_t bh[4][4], bl[4][4];
        #pragma unroll
        for (int p = 0; p < 4; p++) {
            LDMX4(bh[p], BhiS + bBase + (uint32_t)(p * 16) * RSB + kb);
            LDMX4(bl[p], BloS + bBase + (uint32_t)(p * 16) * RSB + kb);
        }
        #pragma unroll
        for (int p = 0; p < 4; p++) {
            #pragma unroll
            for (int hn = 0; hn < 2; hn++) {
                const int ni = p * 2 + hn;
                #pragma unroll
                for (int mi = 0; mi < 2; mi++) {
                    mma16816(acc[mi][ni], ah[mi], &bh[p][hn * 2]);
                    mma16816(acc[mi][ni], al[mi], &bh[p][hn * 2]);
                    mma16816(acc[mi][ni], ah[mi], &bl[p][hn * 2]);
                }
            }
        }
    }

    // -------- epilogue: bias (+relu), float2 stores --------
    const bool relu = (mode == 1);
    #pragma unroll
    for (int mi = 0; mi < 2; mi++) {
        const int r0 = token0 + wm * 32 + mi * 16 + g;
        #pragma unroll
        for (int ni = 0; ni < 8; ni++) {
            const int col = wn * 64 + ni * 8 + 2 * t;
            const float bx = sm[col], by = sm[col + 1];
            float2 v0, v1;
            v0.x = acc[mi][ni][0] + bx; v0.y = acc[mi][ni][1] + by;
            v1.x = acc[mi][ni][2] + bx; v1.y = acc[mi][ni][3] + by;
            if (relu) {
                v0.x = fmaxf(v0.x, 0.f); v0.y = fmaxf(v0.y, 0.f);
                v1.x = fmaxf(v1.x, 0.f); v1.y = fmaxf(v1.y, 0.f);
            }
            *(float2*)(out + (size_t)r0 * DIM + col) = v0;
            *(float2*)(out + (size_t)(r0 + 8) * DIM + col) = v1;
        }
    }
}

// ---------------------------------------------------------------------------
// Pool partials + classifier
// ---------------------------------------------------------------------------
__global__ __launch_bounds__(128) void pool_part_kernel(const float* __restrict__ h)
{
    const int b = blockIdx.x >> 3, j = blockIdx.x & 7;
    const int tid = threadIdx.x;
    const float* base = h + ((size_t)b * SEQ + j * 256) * DIM;
    float s = 0.f;
    #pragma unroll 8
    for (int r = 0; r < 256; r++) s += base[(size_t)r * DIM + tid];
    g_part[blockIdx.x * DIM + tid] = s;
}

__global__ __launch_bounds__(128) void cls_kernel(
    const float* __restrict__ w1, const float* __restrict__ b1,
    const float* __restrict__ w2, const float* __restrict__ b2,
    float* __restrict__ out)
{
    __shared__ float P[128];
    __shared__ float C1[64];
    const int b = blockIdx.x, tid = threadIdx.x;
    float s = 0.f;
    #pragma unroll
    for (int j = 0; j < 8; j++) s += g_part[(b * 8 + j) * DIM + tid];
    P[tid] = s * (1.0f / (float)SEQ);
    __syncthreads();
    if (tid < 64) {
        float a = b1[tid];
        #pragma unroll 8
        for (int k = 0; k < 128; k++) a += P[k] * w1[k * 64 + tid];
        C1[tid] = fmaxf(a, 0.f);
    }
    __syncthreads();
    if (tid < 3) {
        float a = b2[tid];
        #pragma unroll
        for (int k = 0; k < 64; k++) a += C1[k] * w2[k * 3 + tid];
        out[b * 3 + tid] = a;
    }
}

extern "C" void kernel_launch(void* const* d_in, const int* in_sizes, int n_in,
                              void* d_out, int out_size)
{
    const float* x      = (const float*)d_in[0];
    const float* enc_w1 = (const float*)d_in[1];
    const float* enc_b1 = (const float*)d_in[2];
    const float* enc_w2 = (const float*)d_in[3];
    const float* enc_b2 = (const float*)d_in[4];
    const float* gc1_w  = (const float*)d_in[5];
    const float* gc1_b  = (const float*)d_in[6];
    const float* gc2_w  = (const float*)d_in[7];
    const float* gc2_b  = (const float*)d_in[8];
    const float* gc3_w  = (const float*)d_in[9];
    const float* gc3_b  = (const float*)d_in[10];
    const float* cls_w1 = (const float*)d_in[11];
    const float* cls_b1 = (const float*)d_in[12];
    const float* cls_w2 = (const float*)d_in[13];
    const float* cls_b2 = (const float*)d_in[14];
    float* out = (float*)d_out;

    void *p0, *p1, *pbh, *pbl;
    cudaGetSymbolAddress(&p0, g_h0);
    cudaGetSymbolAddress(&p1, g_h1);
    cudaGetSymbolAddress(&pbh, g_Bhi);
    cudaGetSymbolAddress(&pbl, g_Blo);
    float* h0 = (float*)p0;
    float* h1 = (float*)p1;
    const __nv_bfloat16* Bhi = (const __nv_bfloat16*)pbh;
    const __nv_bfloat16* Blo = (const __nv_bfloat16*)pbl;

    const size_t stage_sm = 4096 + 4 * (size_t)DIM * RSB;
    cudaFuncSetAttribute(stage_kernel, cudaFuncAttributeMaxDynamicSharedMemorySize, (int)stage_sm);

    prep_w<<<4, 256>>>(enc_w2, gc1_w, gc2_w, gc3_w);

    const int nblk = NTOK / 128;   // 512
    stage_kernel<<<nblk, 256, stage_sm>>>(x,  Bhi + 0 * DIM * DIM, Blo + 0 * DIM * DIM, enc_b2, enc_w1, enc_b1, h0, 0);
    stage_kernel<<<nblk, 256, stage_sm>>>(h0, Bhi + 1 * DIM * DIM, Blo + 1 * DIM * DIM, gc1_b,  enc_w1, enc_b1, h1, 1);
    stage_kernel<<<nblk, 256, stage_sm>>>(h1, Bhi + 2 * DIM * DIM, Blo + 2 * DIM * DIM, gc2_b,  enc_w1, enc_b1, h0, 1);
    stage_kernel<<<nblk, 256, stage_sm>>>(h0, Bhi + 3 * DIM * DIM, Blo + 3 * DIM * DIM, gc3_b,  enc_w1, enc_b1, h1, 1);
    pool_part_kernel<<<NB * 8, 128>>>(h1);
    cls_kernel<<<NB, 128>>>(cls_w1, cls_b1, cls_w2, cls_b2, out);
}